// round 14
// baseline (speedup 1.0000x reference)
#include <cuda_runtime.h>
#include <cuda_bf16.h>
#include <cstdint>
#include <math.h>

#define TS 63
#define B 32
#define S 256
#define H 512
#define V 32000
#define NG (V/16)              /* 2000 gen A-row groups */
#define KC (H/16)              /* 32 bf16 k-chunks */
#define XFRAG (4*KC*32*4)      /* bf16 X image: uint32 count */
#define GENB 250               /* V/128 generator blocks */
#define L0B 64                 /* 512 layer-0 warp jobs / 8 */

// ------------------------- device scratch -----------------------------------
__device__ float g_h0[2][B*H];      // ping-pong: [t&1] = new at step t
__device__ float g_h1[2][B*H];
__device__ float g_c[2][B*H];
__device__ float g_emb[TS][B*H];
__device__ float g_dec[B*H];
__device__ float g_ctx[B*H];
__device__ float g_WaT[H*H];
__device__ float g_sumZ[TS*B];
// bf16 generator fragments (proven R9/R11)
__device__ __align__(16) uint32_t g_Wq[(size_t)NG*KC*32*8];
__device__ __align__(16) uint32_t g_xq[XFRAG];

// ------------------------- helpers -------------------------------------------
__device__ __forceinline__ void mma16816(float c[4], const uint32_t a[4],
                                         uint32_t b0, uint32_t b1) {
    asm volatile("mma.sync.aligned.m16n8k16.row.col.f32.bf16.bf16.f32 "
        "{%0,%1,%2,%3}, {%4,%5,%6,%7}, {%8,%9}, {%0,%1,%2,%3};"
        : "+f"(c[0]), "+f"(c[1]), "+f"(c[2]), "+f"(c[3])
        : "r"(a[0]), "r"(a[1]), "r"(a[2]), "r"(a[3]), "r"(b0), "r"(b1));
}
__device__ __forceinline__ uint32_t pack_bf16(float x, float y) {
    __nv_bfloat162 v = __floats2bfloat162_rn(x, y);
    return *reinterpret_cast<uint32_t*>(&v);
}
__device__ __forceinline__ float bf16_hi_f(float x) {
    __nv_bfloat16 h = __float2bfloat16_rn(x);
    return __bfloat162float(h);
}
__device__ __forceinline__ void scatter_frag(uint32_t* base, int b, int k, float v) {
    int bg = b >> 3, gid = b & 7;
    int c = k >> 4, kk = k & 15;
    int hi8 = kk >> 3, tig = (kk >> 1) & 3, half = kk & 1;
    int lane = gid*4 + tig;
    int idx2 = (bg*KC + c)*32 + lane;
    __nv_bfloat16 hb = __float2bfloat16_rn(v);
    float hv = __bfloat162float(hb);
    __nv_bfloat16 lb = __float2bfloat16_rn(v - hv);
    unsigned short* p16 = reinterpret_cast<unsigned short*>(base);
    p16[(idx2*4 + hi8)*2 + half]     = *reinterpret_cast<unsigned short*>(&hb);
    p16[(idx2*4 + 2 + hi8)*2 + half] = *reinterpret_cast<unsigned short*>(&lb);
}
__device__ __forceinline__ float sigm(float x) { return 1.f/(1.f+expf(-x)); }

// ------------------------- fp32 warp GEMV (wc path) --------------------------
__device__ __forceinline__ void warp_gemv_acc(const float* __restrict__ Wrow,
                                              const float* __restrict__ X,
                                              float acc[B]) {
    const int lane = threadIdx.x & 31;
#pragma unroll
    for (int kk = 0; kk < 4; kk++) {
        const int k = kk*128 + lane*4;
        const float4 w = *reinterpret_cast<const float4*>(Wrow + k);
#pragma unroll
        for (int b = 0; b < B; b++) {
            const float4 x = *reinterpret_cast<const float4*>(X + b*H + k);
            acc[b] += w.x*x.x + w.y*x.y + w.z*x.z + w.w*x.w;
        }
    }
}
__device__ __forceinline__ float warp_reduce_b(float acc[B], float* sm) {
    const int lane = threadIdx.x & 31;
#pragma unroll
    for (int b = 0; b < B; b++) sm[b*33 + lane] = acc[b];
    __syncwarp();
    float s = 0.f;
#pragma unroll
    for (int j = 0; j < 32; j++) s += sm[lane*33 + j];
    return s;
}

// ------------------------- fused 4-gate LSTM warp ----------------------------
// One warp owns hidden index j: computes gates i,f,g,o for all 32 batches over
// nseg K-segments, applies the activation, writes h_new (ping-pong) and c.
__device__ void lstm_warp(int j, int nseg,
                          const float* const* Xs,
                          const float* const* Ws, size_t wstride,
                          const float* __restrict__ bias,
                          float* __restrict__ cbuf,
                          float* __restrict__ hnew,
                          float* sm /* >=528 floats */) {
    const int lane = threadIdx.x & 31;
    float gv[4];
#pragma unroll
    for (int r = 0; r < 4; r++) gv[r] = bias[r*512 + j];

    for (int half = 0; half < 2; half++) {
        float acc[4][16];
#pragma unroll
        for (int r = 0; r < 4; r++)
#pragma unroll
            for (int bi = 0; bi < 16; bi++) acc[r][bi] = 0.f;

        for (int seg = 0; seg < nseg; seg++) {
            const float* X  = Xs[seg];
            const float* W0 = Ws[seg];
#pragma unroll
            for (int kk = 0; kk < 4; kk++) {
                const int k = kk*128 + lane*4;
                float4 w4[4];
#pragma unroll
                for (int r = 0; r < 4; r++)
                    w4[r] = *reinterpret_cast<const float4*>(W0 + (size_t)r*512*wstride + k);
#pragma unroll
                for (int bi = 0; bi < 16; bi++) {
                    const int b = half*16 + bi;
                    float4 x4 = *reinterpret_cast<const float4*>(X + b*H + k);
#pragma unroll
                    for (int r = 0; r < 4; r++)
                        acc[r][bi] += w4[r].x*x4.x + w4[r].y*x4.y
                                    + w4[r].z*x4.z + w4[r].w*x4.w;
                }
            }
        }
        // cross-lane reduce: lane b ends with sum for batch b
#pragma unroll
        for (int r = 0; r < 4; r++) {
            __syncwarp();
#pragma unroll
            for (int bi = 0; bi < 16; bi++) sm[bi*33 + lane] = acc[r][bi];
            __syncwarp();
            if ((lane >> 4) == half) {
                const int bi = lane & 15;
                float s = 0.f;
#pragma unroll
                for (int i = 0; i < 32; i++) s += sm[bi*33 + i];
                gv[r] += s;
            }
        }
    }
    __syncwarp();
    // LSTM activation for b = lane
    float c  = cbuf[lane*H + j];
    float cn = sigm(gv[1])*c + sigm(gv[0])*tanhf(gv[2]);
    cbuf[lane*H + j] = cn;
    hnew[lane*H + j] = sigm(gv[3])*tanhf(cn);
}

// ------------------------- generator tile (bf16x3, proven) -------------------
__device__ void gen_tile(int tile, int tGen, const float* __restrict__ bgen,
                         float* __restrict__ out, float* Dsm) {
    const int tid = threadIdx.x;
    const int wid = tid >> 5, lane = tid & 31;
    const int gid = lane >> 2, tig = lane & 3;
    const int nt = tile * 128;
    const int ngrp = tile*8 + wid;
    const uint32_t* wq = g_Wq + (size_t)ngrp*KC*32*8;

    float acc[4][4] = {};
    for (int c = 0; c < KC; c++) {
        const uint32_t* ap = wq + (c*32 + lane)*8;
        uint4 ahiv = *reinterpret_cast<const uint4*>(ap);
        uint4 alov = *reinterpret_cast<const uint4*>(ap + 4);
        uint32_t ahi[4] = {ahiv.x, ahiv.y, ahiv.z, ahiv.w};
        uint32_t alo[4] = {alov.x, alov.y, alov.z, alov.w};
#pragma unroll
        for (int bg = 0; bg < 4; bg++) {
            uint4 xb = *reinterpret_cast<const uint4*>(&g_xq[((bg*KC + c)*32 + lane)*4]);
            mma16816(acc[bg], ahi, xb.x, xb.y);
            mma16816(acc[bg], ahi, xb.z, xb.w);
            mma16816(acc[bg], alo, xb.x, xb.y);
        }
    }
#pragma unroll
    for (int bg = 0; bg < 4; bg++) {
#pragma unroll
        for (int r = 0; r < 4; r++) {
            int nl = wid*16 + gid + ((r >= 2) ? 8 : 0);
            int b  = bg*8 + tig*2 + (r & 1);
            Dsm[nl*33 + b] = acc[bg][r];
        }
    }
    __syncthreads();

    const int n = tid & 127, bh = tid >> 7;
    const float bias = bgen[nt + n];
    float* obase = out + (size_t)tGen*B*V + nt + n;
#pragma unroll
    for (int j = 0; j < 16; j++) {
        int b = bh*16 + j;
        float v = Dsm[n*33 + b] + bias;
        obase[(size_t)b*V] = v;
        Dsm[n*33 + b] = expf(v);
    }
    __syncthreads();
    if (tid < 32) {
        float s = 0.f;
#pragma unroll 8
        for (int nn = 0; nn < 128; nn++) s += Dsm[nn*33 + tid];
        atomicAdd(&g_sumZ[tGen*B + tid], s);
    }
}

// ------------------------- kernels ------------------------------------------
__global__ void __launch_bounds__(256) k_init(const float* __restrict__ eh,
                                              const float* __restrict__ ec,
                                              const float* __restrict__ Wa) {
    int idx = blockIdx.x*256 + threadIdx.x;          // grid covers H*H
    if (idx < 2*B*H) {
        (&g_c[0][0])[idx] = ec[idx];
        int layer = idx >> 14;
        int rem = idx & (B*H - 1);
        if (layer == 0) g_h0[1][rem] = eh[idx];       // "prev" for t=0
        else            g_h1[1][rem] = eh[idx];
    }
    if (idx < B*H)   g_dec[idx] = 0.f;
    if (idx < TS*B)  g_sumZ[idx] = 0.f;
    if (idx < H*H)   { int h = idx / H; int k = idx - h*H; g_WaT[k*H + h] = Wa[idx]; }
}

__global__ void __launch_bounds__(256) k_embed(const int* __restrict__ tgt,
                                               const float* __restrict__ et) {
    int idx = blockIdx.x*256 + threadIdx.x;          // < TS*B*H
    int e = idx & (H - 1);
    int r = idx >> 9;
    int tok = tgt[r];
    (&g_emb[0][0])[idx] = et[(size_t)tok*H + e];
}

// bf16 gen weight pack (proven)
__global__ void __launch_bounds__(256) k_pack(const float* __restrict__ Wgen) {
    int idx = blockIdx.x*256 + threadIdx.x;
    int reg  = idx & 7;
    int lane = (idx >> 3) & 31;
    int c    = (idx >> 8) & 31;
    int g    = idx >> 13;
    int split = reg >> 2, r4 = reg & 3;
    int gid = lane >> 2, tig = lane & 3;
    int n = g*16 + gid + ((r4 & 1) ? 8 : 0);
    int k = c*16 + tig*2 + ((r4 & 2) ? 8 : 0);
    float w0 = Wgen[(size_t)n*H + k];
    float w1 = Wgen[(size_t)n*H + k + 1];
    float h0 = bf16_hi_f(w0), h1 = bf16_hi_f(w1);
    g_Wq[idx] = (split == 0) ? pack_bf16(h0, h1) : pack_bf16(w0 - h0, w1 - h1);
}

// shared union for the merged kernel
union MixSmem {
    float Dsm[128*33];      // 16896 B (gen)
    float gsm[8][544];      // 17408 B (gates)
};

// Merged: generator(t-1) blocks [0, GENB) + fused layer-0 LSTM (512 warp jobs).
__global__ void __launch_bounds__(256) k_mix(const float* __restrict__ Wx0,
                                             const float* __restrict__ Wh0,
                                             const float* __restrict__ b0v,
                                             const float* __restrict__ bgen,
                                             float* __restrict__ out,
                                             int t, int tGen) {
    __shared__ MixSmem u;
    if ((int)blockIdx.x < GENB) {
        if (tGen >= 0) gen_tile(blockIdx.x, tGen, bgen, out, u.Dsm);
        return;
    }
    const int wid = threadIdx.x >> 5;
    const int j = (blockIdx.x - GENB)*8 + wid;        // 0..511
    const int cur = t & 1, prv = cur ^ 1;
    const float* Xs[3] = { g_emb[t], g_dec, g_h0[prv] };
    const float* Ws[3] = { Wx0 + (size_t)j*1024,
                           Wx0 + (size_t)j*1024 + 512,
                           Wh0 + (size_t)j*512 };
    // NOTE: Ws row stride differs per seg; handle via two calls is wasteful —
    // instead wstride trick: seg2 uses 512 stride. We inline by splitting:
    // lstm_warp assumes uniform wstride, so pass segments with matching stride.
    // Wx0 rows are 1024 apart, Wh0 rows 512 apart -> use per-seg stride array.
    // (lstm_warp handles this via Wstrides array below.)
    const float* XsA[2] = { g_emb[t], g_dec };
    const float* WsA[2] = { Ws[0], Ws[1] };
    // accumulate Wx0 segments (stride 1024), then Wh0 segment (stride 512):
    // implemented via two lstm partial passes is complex; instead do a custom
    // inline loop here mirroring lstm_warp but with per-seg stride.
    const int lane = threadIdx.x & 31;
    float gv[4];
#pragma unroll
    for (int r = 0; r < 4; r++) gv[r] = b0v[r*512 + j];
    for (int half = 0; half < 2; half++) {
        float acc[4][16];
#pragma unroll
        for (int r = 0; r < 4; r++)
#pragma unroll
            for (int bi = 0; bi < 16; bi++) acc[r][bi] = 0.f;
        for (int seg = 0; seg < 3; seg++) {
            const float* X  = Xs[seg];
            const float* W0 = Ws[seg];
            const size_t rstride = (seg < 2) ? (size_t)512*1024 : (size_t)512*512;
#pragma unroll
            for (int kk = 0; kk < 4; kk++) {
                const int k = kk*128 + lane*4;
                float4 w4[4];
#pragma unroll
                for (int r = 0; r < 4; r++)
                    w4[r] = *reinterpret_cast<const float4*>(W0 + (size_t)r*rstride + k);
#pragma unroll
                for (int bi = 0; bi < 16; bi++) {
                    const int b = half*16 + bi;
                    float4 x4 = *reinterpret_cast<const float4*>(X + b*H + k);
#pragma unroll
                    for (int r = 0; r < 4; r++)
                        acc[r][bi] += w4[r].x*x4.x + w4[r].y*x4.y
                                    + w4[r].z*x4.z + w4[r].w*x4.w;
                }
            }
        }
        float* sm = u.gsm[wid];
#pragma unroll
        for (int r = 0; r < 4; r++) {
            __syncwarp();
#pragma unroll
            for (int bi = 0; bi < 16; bi++) sm[bi*33 + lane] = acc[r][bi];
            __syncwarp();
            if ((lane >> 4) == half) {
                const int bi = lane & 15;
                float s = 0.f;
#pragma unroll
                for (int i = 0; i < 32; i++) s += sm[bi*33 + i];
                gv[r] += s;
            }
        }
    }
    __syncwarp();
    float c  = g_c[0][lane*H + j];
    float cn = sigm(gv[1])*c + sigm(gv[0])*tanhf(gv[2]);
    g_c[0][lane*H + j] = cn;
    g_h0[cur][lane*H + j] = sigm(gv[3])*tanhf(cn);
}

// Fused layer-1 LSTM: Wx1*h0_new + Wh1*h1_prev + act, writes h1_new.
__global__ void __launch_bounds__(256) k_l1(const float* __restrict__ Wx1,
                                            const float* __restrict__ Wh1,
                                            const float* __restrict__ b1v, int t) {
    __shared__ float gsm[8][544];
    const int wid = threadIdx.x >> 5;
    const int j = blockIdx.x*8 + wid;                 // 0..511
    const int cur = t & 1, prv = cur ^ 1;
    const float* Xs[2] = { g_h0[cur], g_h1[prv] };
    const float* Ws[2] = { Wx1 + (size_t)j*512, Wh1 + (size_t)j*512 };
    lstm_warp(j, 2, Xs, Ws, 512, b1v, g_c[1], g_h1[cur], gsm[wid]);
}

// Fused: q projection + attention + context (h1 already computed by k_l1).
__global__ void __launch_bounds__(256) k_attn(const float* __restrict__ mb,
                                              const int* __restrict__ mlen,
                                              float* __restrict__ attn_out, int t) {
    __shared__ float sh1[H];
    __shared__ float sq[H];
    __shared__ float al[S];
    __shared__ float red[256];
    const int b = blockIdx.x;
    const int tid = threadIdx.x, warp = tid >> 5, lane = tid & 31;
    const int len = mlen[b];
    const float* h1 = g_h1[t & 1] + (size_t)b*H;

    for (int j = tid; j < H; j += 256) sh1[j] = h1[j];
    __syncthreads();

    for (int n0 = warp; n0 < H; n0 += 8) {
        const float* wr = g_WaT + (size_t)n0*H;
        float a = 0.f;
#pragma unroll
        for (int kk = 0; kk < 4; kk++) {
            int k = kk*128 + lane*4;
            float4 w  = *reinterpret_cast<const float4*>(wr + k);
            float4 hx = *reinterpret_cast<const float4*>(sh1 + k);
            a += w.x*hx.x + w.y*hx.y + w.z*hx.z + w.w*hx.w;
        }
#pragma unroll
        for (int off = 16; off; off >>= 1) a += __shfl_xor_sync(0xffffffffu, a, off);
        if (lane == 0) sq[n0] = a;
    }
    __syncthreads();

    for (int s0 = warp; s0 < S; s0 += 8) {
        const float* m = mb + ((size_t)s0*B + b)*H;
        float a = 0.f;
#pragma unroll
        for (int kk = 0; kk < 4; kk++) {
            int k = kk*128 + lane*4;
            float4 mv = *reinterpret_cast<const float4*>(m + k);
            float4 qv = *reinterpret_cast<const float4*>(sq + k);
            a += mv.x*qv.x + mv.y*qv.y + mv.z*qv.z + mv.w*qv.w;
        }
#pragma unroll
        for (int off = 16; off; off >>= 1) a += __shfl_xor_sync(0xffffffffu, a, off);
        if (lane == 0) al[s0] = (s0 < len) ? a : -1.0e9f;
    }
    __syncthreads();

    float v = al[tid];
    red[tid] = v; __syncthreads();
    for (int o = 128; o; o >>= 1) { if (tid < o) red[tid] = fmaxf(red[tid], red[tid+o]); __syncthreads(); }
    float vmax = red[0];
    __syncthreads();
    float e = expf(v - vmax);
    red[tid] = e; __syncthreads();
    for (int o = 128; o; o >>= 1) { if (tid < o) red[tid] += red[tid+o]; __syncthreads(); }
    float p = e / red[0];
    al[tid] = p;
    attn_out[((size_t)t*B + b)*S + tid] = p;
    __syncthreads();

    for (int k = tid; k < H; k += 256) {
        float acc = 0.f;
#pragma unroll 4
        for (int s = 0; s < S; s++) acc += al[s] * mb[((size_t)s*B + b)*H + k];
        g_ctx[b*H + k] = acc;
    }
}

// Wc projection + tanh; writes fp32 dec and scatters bf16 gen fragments.
__global__ void __launch_bounds__(256) k_wc(const float* __restrict__ Wc, int t) {
    __shared__ float sm[8][33*32];
    const int warp = threadIdx.x >> 5, lane = threadIdx.x & 31;
    const int n = blockIdx.x*8 + warp;                // 0..511
    const float* h1 = g_h1[t & 1];
    float acc[B] = {};
    warp_gemv_acc(Wc + (size_t)n*1024,       g_ctx, acc);
    warp_gemv_acc(Wc + (size_t)n*1024 + 512, h1,    acc);
    float s = warp_reduce_b(acc, sm[warp]);
    float d = tanhf(s);
    g_dec[lane*H + n] = d;
    scatter_frag(g_xq, lane, n, d);
}

__global__ void __launch_bounds__(256) k_lsm(float* __restrict__ out) {
    __shared__ float lz;
    const int t = blockIdx.z, b = blockIdx.y;
    if (threadIdx.x == 0) lz = logf(g_sumZ[t*B + b]);
    __syncthreads();
    int v = blockIdx.x*256 + threadIdx.x;
    out[((size_t)(t*B + b))*V + v] -= lz;
}

// ------------------------- launch -------------------------------------------
extern "C" void kernel_launch(void* const* d_in, const int* in_sizes, int n_in,
                              void* d_out, int out_size) {
    const int*   tgt   = (const int*)  d_in[0];
    const float* mb    = (const float*)d_in[1];
    const int*   mlen  = (const int*)  d_in[2];
    const float* enc_h = (const float*)d_in[3];
    const float* enc_c = (const float*)d_in[4];
    const float* emb   = (const float*)d_in[5];
    const float* Wx0   = (const float*)d_in[6];
    const float* Wh0   = (const float*)d_in[7];
    const float* b0    = (const float*)d_in[8];
    const float* Wx1   = (const float*)d_in[9];
    const float* Wh1   = (const float*)d_in[10];
    const float* b1    = (const float*)d_in[11];
    const float* Wa    = (const float*)d_in[12];
    const float* Wc    = (const float*)d_in[13];
    const float* Wgen  = (const float*)d_in[14];
    const float* bgen  = (const float*)d_in[15];

    float* out      = (float*)d_out;
    float* attn_out = out + (size_t)TS*B*V;

    k_init <<<(H*H + 255)/256, 256>>>(enc_h, enc_c, Wa);
    k_embed<<<(TS*B*H)/256, 256>>>(tgt, emb);
    k_pack <<<NG*32, 256>>>(Wgen);

    for (int t = 0; t < TS; t++) {
        k_mix <<<GENB + L0B, 256>>>(Wx0, Wh0, b0, bgen, out, t, t - 1);
        k_l1  <<<L0B, 256>>>(Wx1, Wh1, b1, t);
        k_attn<<<B, 256>>>(mb, mlen, attn_out, t);
        k_wc  <<<H/8, 256>>>(Wc, t);
    }
    k_mix<<<GENB, 256>>>(Wx0, Wh0, b0, bgen, out, 0, TS - 1);
    k_lsm<<<dim3(V/256, B, TS), 256>>>(out);
}